// round 1
// baseline (speedup 1.0000x reference)
#include <cuda_runtime.h>
#include <cuda_bf16.h>
#include <math.h>

#define NN   8192
#define DEG  8
#define NH   4
#define NF   768
#define NHD  3072
#define ND   768
#define NBG  8
#define NPG  1024
#define NQ   16
#define NROW 128   // NBG*NQ

// ---------------- scratch (static device memory; no allocation) ----------------
__device__ float g_feat[(size_t)NN * NHD];   // GEMM output (feat) per layer
__device__ float g_h[(size_t)NN * NHD];      // layer output h (pre/post LN in place)
__device__ float g_el[NN * NH];
__device__ float g_er[NN * NH];
__device__ float g_m1[(size_t)NN * NF];
__device__ float g_rep[(size_t)NN * NF];
__device__ float g_S[(size_t)NROW * NN];     // all query-node sims
__device__ float g_colsum[NHD];
__device__ float g_colsq[NHD];
__device__ float g_colA[NHD];
__device__ float g_colB[NHD];

// ---------------- SGEMM: C[N x M] = A[N x K] @ B[K x M], row-major ----------------
// Tiles: 128x128x16, 256 threads, 8x8 per thread. All dims divisible.
__global__ __launch_bounds__(256) void sgemm_kernel(
    const float* __restrict__ A, const float* __restrict__ B,
    float* __restrict__ C, int K, int M)
{
    __shared__ float As[16][128];
    __shared__ float Bs[16][128];
    int tid = threadIdx.x;
    int bx = blockIdx.x, by = blockIdx.y;
    const float* Ab = A + (size_t)by * 128 * K;
    const float* Bb = B + (size_t)bx * 128;
    float acc[8][8];
#pragma unroll
    for (int i = 0; i < 8; i++)
#pragma unroll
        for (int j = 0; j < 8; j++) acc[i][j] = 0.f;

    int ty = tid >> 4, tx = tid & 15;

    for (int k0 = 0; k0 < K; k0 += 16) {
#pragma unroll
        for (int i = 0; i < 2; i++) {
            int li = tid + i * 256;          // 0..511
            int ar = li >> 2;                // 0..127
            int ac = (li & 3) * 4;           // 0,4,8,12
            float4 v = *(const float4*)(Ab + (size_t)ar * K + k0 + ac);
            As[ac + 0][ar] = v.x; As[ac + 1][ar] = v.y;
            As[ac + 2][ar] = v.z; As[ac + 3][ar] = v.w;
        }
#pragma unroll
        for (int i = 0; i < 2; i++) {
            int li = tid + i * 256;
            int br = li >> 5;                // 0..15
            int bc = (li & 31) * 4;          // 0..124
            float4 v = *(const float4*)(Bb + (size_t)(k0 + br) * M + bc);
            *(float4*)(&Bs[br][bc]) = v;
        }
        __syncthreads();
#pragma unroll
        for (int k = 0; k < 16; k++) {
            float ra[8], rb[8];
            *(float4*)(ra)     = *(const float4*)(&As[k][ty * 8]);
            *(float4*)(ra + 4) = *(const float4*)(&As[k][ty * 8 + 4]);
            *(float4*)(rb)     = *(const float4*)(&Bs[k][tx * 8]);
            *(float4*)(rb + 4) = *(const float4*)(&Bs[k][tx * 8 + 4]);
#pragma unroll
            for (int i = 0; i < 8; i++)
#pragma unroll
                for (int j = 0; j < 8; j++)
                    acc[i][j] += ra[i] * rb[j];
        }
        __syncthreads();
    }

    float* Cb = C + (size_t)(by * 128 + ty * 8) * M + bx * 128 + tx * 8;
#pragma unroll
    for (int i = 0; i < 8; i++) {
        float4 v0 = make_float4(acc[i][0], acc[i][1], acc[i][2], acc[i][3]);
        float4 v1 = make_float4(acc[i][4], acc[i][5], acc[i][6], acc[i][7]);
        *(float4*)(Cb + (size_t)i * M)     = v0;
        *(float4*)(Cb + (size_t)i * M + 4) = v1;
    }
}

// ---------------- el/er: per (n,h) dot of feat row with attn vectors ----------------
__global__ __launch_bounds__(256) void elr_kernel(
    const float* __restrict__ feat, const float* __restrict__ al,
    const float* __restrict__ ar, float* __restrict__ el, float* __restrict__ er)
{
    int gw = (blockIdx.x * blockDim.x + threadIdx.x) >> 5;
    int lane = threadIdx.x & 31;
    if (gw >= NN * NH) return;
    int n = gw >> 2, h = gw & 3;
    const float* f   = feat + (size_t)n * NHD + h * NF;
    const float* alh = al + h * NF;
    const float* arh = ar + h * NF;
    float sl = 0.f, sr = 0.f;
    for (int i = lane; i < NF; i += 32) {
        float v = f[i];
        sl += v * alh[i];
        sr += v * arh[i];
    }
#pragma unroll
    for (int o = 16; o; o >>= 1) {
        sl += __shfl_xor_sync(0xffffffffu, sl, o);
        sr += __shfl_xor_sync(0xffffffffu, sr, o);
    }
    if (lane == 0) { el[gw] = sl; er[gw] = sr; }
}

// ---------------- edge softmax + aggregation (+bias) ----------------
// edge_dst = repeat(arange(N), 8): node n owns edges [8n, 8n+8)
__global__ __launch_bounds__(256) void aggregate_kernel(
    const float* __restrict__ feat, const float* __restrict__ el,
    const float* __restrict__ er, const int* __restrict__ esrc,
    const float* __restrict__ bias, float* __restrict__ out)
{
    int n = blockIdx.x;
    __shared__ int   ssrc[DEG];
    __shared__ float salpha[NH * DEG];
    int tid = threadIdx.x;
    if (tid < DEG) ssrc[tid] = esrc[n * DEG + tid];
    __syncthreads();
    if (tid < 32) {
        int h = tid >> 3, k = tid & 7;
        float e = el[ssrc[k] * NH + h] + er[n * NH + h];
        e = e > 0.f ? e : 0.2f * e;
        float m = e;
#pragma unroll
        for (int o = 4; o; o >>= 1) m = fmaxf(m, __shfl_xor_sync(0xffffffffu, m, o));
        float a = __expf(e - m);
        float s = a;
#pragma unroll
        for (int o = 4; o; o >>= 1) s += __shfl_xor_sync(0xffffffffu, s, o);
        salpha[tid] = a / s;   // tid == h*8+k
    }
    __syncthreads();
    for (int c = tid; c < NHD; c += 256) {
        int h = c / NF;
        float acc = bias[c];
#pragma unroll
        for (int k = 0; k < DEG; k++)
            acc += salpha[h * DEG + k] * feat[(size_t)ssrc[k] * NHD + c];
        out[(size_t)n * NHD + c] = acc;
    }
}

// ---------------- column stats (LayerNorm over axis 0) ----------------
__global__ void colzero_kernel() {
    int c = blockIdx.x * 256 + threadIdx.x;
    if (c < NHD) { g_colsum[c] = 0.f; g_colsq[c] = 0.f; }
}

__global__ __launch_bounds__(256) void colstats_kernel(const float* __restrict__ x) {
    int c  = blockIdx.x * 256 + threadIdx.x;
    int r0 = blockIdx.y * 256;
    float s = 0.f, s2 = 0.f;
    for (int r = r0; r < r0 + 256; r++) {
        float v = x[(size_t)r * NHD + c];
        s += v; s2 += v * v;
    }
    atomicAdd(&g_colsum[c], s);
    atomicAdd(&g_colsq[c], s2);
}

__global__ void colfin_kernel(const float* __restrict__ gamma, const float* __restrict__ beta) {
    int c = blockIdx.x * 256 + threadIdx.x;
    if (c >= NHD) return;
    float mu  = g_colsum[c] * (1.f / NN);
    float var = g_colsq[c] * (1.f / NN) - mu * mu;
    float rs  = rsqrtf(var + 1e-5f);
    float a   = rs * gamma[c];
    g_colA[c] = a;
    g_colB[c] = beta[c] - mu * a;
}

__global__ __launch_bounds__(256) void lnprelu_kernel(float* __restrict__ x, const float* __restrict__ pa) {
    int n = blockIdx.x;
    for (int c = threadIdx.x; c < NHD; c += 256) {
        float y = g_colA[c] * x[(size_t)n * NHD + c] + g_colB[c];
        x[(size_t)n * NHD + c] = y > 0.f ? y : pa[c] * y;
    }
}

// ---------------- head means / node_rep ----------------
__global__ __launch_bounds__(256) void headmean_kernel(const float* __restrict__ h, float* __restrict__ m) {
    int n = blockIdx.x;
    const float* r = h + (size_t)n * NHD;
    for (int f = threadIdx.x; f < NF; f += 256)
        m[(size_t)n * NF + f] = 0.25f * (r[f] + r[NF + f] + r[2 * NF + f] + r[3 * NF + f]);
}

__global__ __launch_bounds__(256) void repmax_kernel(const float* __restrict__ h) {
    int n = blockIdx.x;
    const float* r = h + (size_t)n * NHD;
    for (int f = threadIdx.x; f < NF; f += 256) {
        float m2 = 0.25f * (r[f] + r[NF + f] + r[2 * NF + f] + r[3 * NF + f]);
        g_rep[(size_t)n * NF + f] = fmaxf(g_m1[(size_t)n * NF + f], m2);
    }
}

// ---------------- sims: S[128 x 8192] = Qe @ rep^T (both K-contiguous) ----------------
__global__ __launch_bounds__(256) void simgemm_kernel(
    const float* __restrict__ Qe, const float* __restrict__ R)
{
    __shared__ float Qs[128][33];
    __shared__ float Rs[32][33];
    int tid = threadIdx.x;
    int n0 = blockIdx.x * 32;
    float acc[16];
#pragma unroll
    for (int i = 0; i < 16; i++) acc[i] = 0.f;
    int n = tid & 31, rb = tid >> 5;   // n: node within tile, rb: query base (0..7)

    for (int k0 = 0; k0 < ND; k0 += 32) {
#pragma unroll
        for (int t = 0; t < 16; t++) {
            int li = tid + t * 256;
            Qs[li >> 5][li & 31] = Qe[(size_t)(li >> 5) * ND + k0 + (li & 31)];
        }
#pragma unroll
        for (int t = 0; t < 4; t++) {
            int li = tid + t * 256;
            Rs[li >> 5][li & 31] = R[(size_t)(n0 + (li >> 5)) * ND + k0 + (li & 31)];
        }
        __syncthreads();
#pragma unroll
        for (int kk = 0; kk < 32; kk++) {
            float b = Rs[n][kk];
#pragma unroll
            for (int i = 0; i < 16; i++)
                acc[i] += Qs[rb + 8 * i][kk] * b;
        }
        __syncthreads();
    }
#pragma unroll
    for (int i = 0; i < 16; i++)
        g_S[(size_t)(rb + 8 * i) * NN + n0 + n] = acc[i];
}

// ---------------- output zero ----------------
__global__ void zeroout_kernel(float* out) {
    if (threadIdx.x < 3) out[threadIdx.x] = 0.f;
}

// ---------------- losses ----------------
__device__ __forceinline__ float warpSumF(float v) {
#pragma unroll
    for (int o = 16; o; o >>= 1) v += __shfl_xor_sync(0xffffffffu, v, o);
    return v;
}

__device__ __forceinline__ float blockSumF(float v, float* sred, int tid) {
    v = warpSumF(v);
    if ((tid & 31) == 0) sred[tid >> 5] = v;
    __syncthreads();
    if (tid < 32) {
        float x = (tid < 16) ? sred[tid] : 0.f;
        x = warpSumF(x);
        if (tid == 0) sred[0] = x;
    }
    __syncthreads();
    float r = sred[0];
    __syncthreads();
    return r;
}

__device__ __forceinline__ float blockMaxF(float v, float* sred, int tid) {
#pragma unroll
    for (int o = 16; o; o >>= 1) v = fmaxf(v, __shfl_xor_sync(0xffffffffu, v, o));
    if ((tid & 31) == 0) sred[tid >> 5] = v;
    __syncthreads();
    if (tid < 32) {
        float x = (tid < 16) ? sred[tid] : -INFINITY;
#pragma unroll
        for (int o = 16; o; o >>= 1) x = fmaxf(x, __shfl_xor_sync(0xffffffffu, x, o));
        if (tid == 0) sred[0] = x;
    }
    __syncthreads();
    float r = sred[0];
    __syncthreads();
    return r;
}

// bitonic sort, descending by key, ties broken by ascending idx (stable-equivalent)
__device__ void bitonic1024_desc(float* key, int* idx, int tid) {
    for (int k = 2; k <= 1024; k <<= 1) {
        for (int j = k >> 1; j > 0; j >>= 1) {
#pragma unroll 1
            for (int t = tid; t < 1024; t += 512) {
                int x = t ^ j;
                if (x > t) {
                    bool descSeg = ((t & k) == 0);
                    float ka = key[t], kb = key[x];
                    int   ia = idx[t], ib = idx[x];
                    bool aFirst = (ka > kb) || (ka == kb && ia < ib);
                    bool doSwap = descSeg ? (!aFirst) : aFirst;
                    if (doSwap) { key[t] = kb; key[x] = ka; idx[t] = ib; idx[x] = ia; }
                }
            }
            __syncthreads();
        }
    }
}

__global__ __launch_bounds__(512) void loss_kernel(const float* __restrict__ bert, float* __restrict__ out) {
    __shared__ float skey[1024];
    __shared__ int   sidx[1024];
    __shared__ float sred[16];
    __shared__ float sh_psim;
    int r = blockIdx.x;                 // 0..127 (graph-major: r = g*16+q)
    int g = r >> 4;
    int base = g * NPG;
    int tid = threadIdx.x;
    const float* Srow = g_S + (size_t)r * NN;

    // 1) sort bert scores descending -> order
    skey[tid]       = bert[(size_t)r * NPG + tid];       sidx[tid]       = tid;
    skey[tid + 512] = bert[(size_t)r * NPG + tid + 512]; sidx[tid + 512] = tid + 512;
    __syncthreads();
    bitonic1024_desc(skey, sidx, tid);

    // 2) gather sims in bert order; payload becomes bert rank
    int i0 = sidx[tid], i1 = sidx[tid + 512];
    float v0 = Srow[base + i0], v1 = Srow[base + i1];
    __syncthreads();
    skey[tid] = v0;       sidx[tid] = tid;
    skey[tid + 512] = v1; sidx[tid + 512] = tid + 512;
    if (tid == 0) sh_psim = v0;         // sim of bert-rank-0 item
    __syncthreads();

    // 3) sort by predicted sim descending (payload = bert rank)
    bitonic1024_desc(skey, sidx, tid);

    // 4) pairwise lambda-MRR over unordered pairs:
    //    t = min(yp_i - yp_j, 50); loss = softplus(-t) + (rank_i > rank_j ? t : 0)
    float L = 0.f;
    for (int i = 0; i < 1023; i++) {
        float yi = skey[i];
        int   pi = sidx[i];
        for (int j = i + 1 + tid; j < 1024; j += 512) {
            float s = yi - skey[j];
            float t = fminf(s, 50.f);
            float u = __logf(1.f + __expf(-t));
            L += u + ((pi > sidx[j]) ? t : 0.f);
        }
    }
    float Ltot = blockSumF(L, sred, tid);

    // 5) row-wide logsumexp (cl) and own-segment entropy
    float mx = -INFINITY;
    for (int c = tid; c < NN; c += 512) mx = fmaxf(mx, Srow[c]);
    float m = blockMaxF(mx, sred, tid);

    float se = 0.f, s1 = 0.f, s2 = 0.f;
    for (int c = tid; c < NN; c += 512) {
        float x = Srow[c] - m;
        float e = __expf(x);
        se += e;
        if (c >= base && c < base + NPG) { s1 += e; s2 += x * e; }
    }
    se = blockSumF(se, sred, tid);
    s1 = blockSumF(s1, sred, tid);
    s2 = blockSumF(s2, sred, tid);

    if (tid == 0) {
        float lse = m + __logf(se);
        float cl  = lse - sh_psim;                  // -log(pe/(pe+ne))
        float ent = __logf(s1) - s2 / s1;           // entropy of softmax over own nodes
        atomicAdd(out + 0, cl  * (1.f / 128.f));
        atomicAdd(out + 2, ent * (1.f / 128.f));
        atomicAdd(out + 1, Ltot * (1.f / 67043328.f)); // / (BG * Q * NPG*(NPG-1)/2)
    }
}

// ---------------- launch ----------------
extern "C" void kernel_launch(void* const* d_in, const int* in_sizes, int n_in,
                              void* d_out, int out_size) {
    const float* x      = (const float*)d_in[0];
    const int*   esrc   = (const int*)d_in[1];
    // d_in[2] = edge_dst (structure known: repeat(arange(N), 8)) — unused
    const float* qe     = (const float*)d_in[3];
    const float* bert   = (const float*)d_in[4];
    const float* W1     = (const float*)d_in[5];
    const float* al1    = (const float*)d_in[6];
    const float* ar1    = (const float*)d_in[7];
    const float* b1     = (const float*)d_in[8];
    const float* gamma1 = (const float*)d_in[9];
    const float* beta1  = (const float*)d_in[10];
    const float* pa1    = (const float*)d_in[11];
    const float* W2     = (const float*)d_in[12];
    const float* al2    = (const float*)d_in[13];
    const float* ar2    = (const float*)d_in[14];
    const float* b2     = (const float*)d_in[15];
    const float* gamma2 = (const float*)d_in[16];
    const float* beta2  = (const float*)d_in[17];
    const float* pa2    = (const float*)d_in[18];
    float* out = (float*)d_out;

    float *feat, *h, *el, *er, *m1, *rep;
    cudaGetSymbolAddress((void**)&feat, g_feat);
    cudaGetSymbolAddress((void**)&h,    g_h);
    cudaGetSymbolAddress((void**)&el,   g_el);
    cudaGetSymbolAddress((void**)&er,   g_er);
    cudaGetSymbolAddress((void**)&m1,   g_m1);
    cudaGetSymbolAddress((void**)&rep,  g_rep);

    dim3 gGemm(NHD / 128, NN / 128);       // (24, 64)
    dim3 gStats(NHD / 256, NN / 256);      // (12, 32)

    zeroout_kernel<<<1, 32>>>(out);

    // ---- layer 1 ----
    sgemm_kernel<<<gGemm, 256>>>(x, W1, feat, ND, NHD);
    elr_kernel<<<(NN * NH) / 8, 256>>>(feat, al1, ar1, el, er);
    aggregate_kernel<<<NN, 256>>>(feat, el, er, esrc, b1, h);
    colzero_kernel<<<NHD / 256, 256>>>();
    colstats_kernel<<<gStats, 256>>>(h);
    colfin_kernel<<<NHD / 256, 256>>>(gamma1, beta1);
    lnprelu_kernel<<<NN, 256>>>(h, pa1);
    headmean_kernel<<<NN, 256>>>(h, m1);

    // ---- layer 2 ----
    sgemm_kernel<<<gGemm, 256>>>(h, W2, feat, NHD, NHD);
    elr_kernel<<<(NN * NH) / 8, 256>>>(feat, al2, ar2, el, er);
    aggregate_kernel<<<NN, 256>>>(feat, el, er, esrc, b2, h);
    colzero_kernel<<<NHD / 256, 256>>>();
    colstats_kernel<<<gStats, 256>>>(h);
    colfin_kernel<<<NHD / 256, 256>>>(gamma2, beta2);
    lnprelu_kernel<<<NN, 256>>>(h, pa2);
    repmax_kernel<<<NN, 256>>>(h);

    // ---- similarities + losses ----
    simgemm_kernel<<<NN / 32, 256>>>(qe, rep);
    loss_kernel<<<NROW, 512>>>(bert, out);
}

// round 4
// speedup vs baseline: 2.6550x; 2.6550x over previous
#include <cuda_runtime.h>
#include <cuda_bf16.h>
#include <math.h>
#include <stdint.h>

#define NN   8192
#define DEG  8
#define NH   4
#define NF   768
#define NHD  3072
#define ND   768
#define NBG  8
#define NPG  1024
#define NQ   16
#define NROW 128   // NBG*NQ

// ---------------- scratch (static device memory; no allocation) ----------------
__device__ float g_feat[(size_t)NN * NHD];   // GEMM output (feat) per layer
__device__ float g_h[(size_t)NN * NHD];      // layer output h (pre/post LN in place)
__device__ float g_el[NN * NH];
__device__ float g_er[NN * NH];
__device__ float g_m1[(size_t)NN * NF];
__device__ float g_rep[(size_t)NN * NF];
__device__ float g_S[(size_t)NROW * NN];     // all query-node sims
__device__ float g_colsum[NHD];
__device__ float g_colsq[NHD];
__device__ float g_colA[NHD];
__device__ float g_colB[NHD];

// ================= tf32 tensor-core GEMM =================
// C[N x M] = A[N x K] @ B[K x M], row-major. BM=BN=128, BK=32.
// 128 threads = 4 warps (2x2), warp tile 64x64, mma.m16n8k8.tf32.
#define GBM 128
#define GBN 128
#define GBK 32
#define ASTR 36     // A smem row stride (floats): banks (4g+tig) -> conflict-free
#define BSTR 136    // B smem row stride (floats): banks (8tig+g) -> conflict-free
#define GEMM_SMEM ((2 * GBM * ASTR + 2 * GBK * BSTR) * 4)

__device__ __forceinline__ void cp_async16(void* dst, const void* src) {
    unsigned int s = (unsigned int)__cvta_generic_to_shared(dst);
    asm volatile("cp.async.cg.shared.global [%0], [%1], 16;" :: "r"(s), "l"(src));
}

__device__ __forceinline__ void gemm_load_tiles(
    float* Asm, float* Bsm, const float* Ab, const float* Bb,
    int buf, int k0, int tid, int K, int M)
{
#pragma unroll
    for (int i = 0; i < 8; i++) {
        int li = tid + i * 128;          // 0..1023
        int r = li >> 3, c4 = li & 7;    // 128 rows x 8 float4
        cp_async16(&Asm[buf * GBM * ASTR + r * ASTR + c4 * 4],
                   Ab + (size_t)r * K + k0 + c4 * 4);
    }
#pragma unroll
    for (int i = 0; i < 8; i++) {
        int li = tid + i * 128;
        int r = li >> 5, c4 = li & 31;   // 32 rows x 32 float4
        cp_async16(&Bsm[buf * GBK * BSTR + r * BSTR + c4 * 4],
                   Bb + (size_t)(k0 + r) * M + c4 * 4);
    }
    asm volatile("cp.async.commit_group;");
}

__global__ __launch_bounds__(128) void mma_gemm_kernel(
    const float* __restrict__ A, const float* __restrict__ B,
    float* __restrict__ C, int K, int M)
{
    extern __shared__ float sm[];
    float* Asm = sm;                         // 2 * 128 * 36
    float* Bsm = sm + 2 * GBM * ASTR;        // 2 * 32 * 136
    int tid = threadIdx.x;
    int lane = tid & 31, wid = tid >> 5;
    int wm = (wid & 1) * 64, wn = (wid >> 1) * 64;
    int g = lane >> 2, tig = lane & 3;
    const float* Ab = A + (size_t)blockIdx.y * GBM * K;
    const float* Bb = B + blockIdx.x * GBN;

    float c[4][8][4];
#pragma unroll
    for (int mt = 0; mt < 4; mt++)
#pragma unroll
        for (int nt = 0; nt < 8; nt++)
#pragma unroll
            for (int i = 0; i < 4; i++) c[mt][nt][i] = 0.f;

    gemm_load_tiles(Asm, Bsm, Ab, Bb, 0, 0, tid, K, M);
    int nk = K / GBK;
    for (int t = 0; t < nk; t++) {
        int buf = t & 1;
        asm volatile("cp.async.wait_group 0;" ::: "memory");
        __syncthreads();
        if (t + 1 < nk)
            gemm_load_tiles(Asm, Bsm, Ab, Bb, buf ^ 1, (t + 1) * GBK, tid, K, M);
        const float* A2 = &Asm[buf * GBM * ASTR];
        const float* B2 = &Bsm[buf * GBK * BSTR];
#pragma unroll
        for (int kk = 0; kk < GBK; kk += 8) {
            unsigned a[4][4], b[8][2];
#pragma unroll
            for (int mt = 0; mt < 4; mt++) {
                int m0 = wm + mt * 16;
                a[mt][0] = __float_as_uint(A2[(m0 + g) * ASTR + kk + tig]);
                a[mt][1] = __float_as_uint(A2[(m0 + g + 8) * ASTR + kk + tig]);
                a[mt][2] = __float_as_uint(A2[(m0 + g) * ASTR + kk + tig + 4]);
                a[mt][3] = __float_as_uint(A2[(m0 + g + 8) * ASTR + kk + tig + 4]);
            }
#pragma unroll
            for (int nt = 0; nt < 8; nt++) {
                int n0 = wn + nt * 8 + g;
                b[nt][0] = __float_as_uint(B2[(kk + tig) * BSTR + n0]);
                b[nt][1] = __float_as_uint(B2[(kk + tig + 4) * BSTR + n0]);
            }
#pragma unroll
            for (int mt = 0; mt < 4; mt++)
#pragma unroll
                for (int nt = 0; nt < 8; nt++)
                    asm volatile(
                        "mma.sync.aligned.m16n8k8.row.col.f32.tf32.tf32.f32 "
                        "{%0,%1,%2,%3}, {%4,%5,%6,%7}, {%8,%9}, {%0,%1,%2,%3};"
                        : "+f"(c[mt][nt][0]), "+f"(c[mt][nt][1]),
                          "+f"(c[mt][nt][2]), "+f"(c[mt][nt][3])
                        : "r"(a[mt][0]), "r"(a[mt][1]), "r"(a[mt][2]), "r"(a[mt][3]),
                          "r"(b[nt][0]), "r"(b[nt][1]));
        }
    }

    float* Cb = C + (size_t)(blockIdx.y * GBM) * M + blockIdx.x * GBN;
#pragma unroll
    for (int mt = 0; mt < 4; mt++)
#pragma unroll
        for (int nt = 0; nt < 8; nt++) {
            int row = wm + mt * 16 + g;
            int col = wn + nt * 8 + 2 * tig;
            *(float2*)(Cb + (size_t)row * M + col) =
                make_float2(c[mt][nt][0], c[mt][nt][1]);
            *(float2*)(Cb + (size_t)(row + 8) * M + col) =
                make_float2(c[mt][nt][2], c[mt][nt][3]);
        }
}

// ---------------- el/er: per (n,h) dot of feat row with attn vectors ----------------
__global__ __launch_bounds__(256) void elr_kernel(
    const float* __restrict__ feat, const float* __restrict__ al,
    const float* __restrict__ ar, float* __restrict__ el, float* __restrict__ er)
{
    int gw = (blockIdx.x * blockDim.x + threadIdx.x) >> 5;
    int lane = threadIdx.x & 31;
    if (gw >= NN * NH) return;
    int n = gw >> 2, h = gw & 3;
    const float* f   = feat + (size_t)n * NHD + h * NF;
    const float* alh = al + h * NF;
    const float* arh = ar + h * NF;
    float sl = 0.f, sr = 0.f;
    for (int i = lane; i < NF; i += 32) {
        float v = f[i];
        sl += v * alh[i];
        sr += v * arh[i];
    }
#pragma unroll
    for (int o = 16; o; o >>= 1) {
        sl += __shfl_xor_sync(0xffffffffu, sl, o);
        sr += __shfl_xor_sync(0xffffffffu, sr, o);
    }
    if (lane == 0) { el[gw] = sl; er[gw] = sr; }
}

// ---------------- edge softmax + aggregation (+bias) ----------------
// edge_dst = repeat(arange(N), 8): node n owns edges [8n, 8n+8)
__global__ __launch_bounds__(256) void aggregate_kernel(
    const float* __restrict__ feat, const float* __restrict__ el,
    const float* __restrict__ er, const int* __restrict__ esrc,
    const float* __restrict__ bias, float* __restrict__ out)
{
    int n = blockIdx.x;
    __shared__ int   ssrc[DEG];
    __shared__ float salpha[NH * DEG];
    int tid = threadIdx.x;
    if (tid < DEG) ssrc[tid] = esrc[n * DEG + tid];
    __syncthreads();
    if (tid < 32) {
        int h = tid >> 3, k = tid & 7;
        float e = el[ssrc[k] * NH + h] + er[n * NH + h];
        e = e > 0.f ? e : 0.2f * e;
        float m = e;
#pragma unroll
        for (int o = 4; o; o >>= 1) m = fmaxf(m, __shfl_xor_sync(0xffffffffu, m, o));
        float a = __expf(e - m);
        float s = a;
#pragma unroll
        for (int o = 4; o; o >>= 1) s += __shfl_xor_sync(0xffffffffu, s, o);
        salpha[tid] = a / s;   // tid == h*8+k
    }
    __syncthreads();
    for (int c = tid; c < NHD; c += 256) {
        int h = c / NF;
        float acc = bias[c];
#pragma unroll
        for (int k = 0; k < DEG; k++)
            acc += salpha[h * DEG + k] * feat[(size_t)ssrc[k] * NHD + c];
        out[(size_t)n * NHD + c] = acc;
    }
}

// ---------------- column stats (LayerNorm over axis 0) ----------------
__global__ void colzero_kernel() {
    int c = blockIdx.x * 256 + threadIdx.x;
    if (c < NHD) { g_colsum[c] = 0.f; g_colsq[c] = 0.f; }
}

__global__ __launch_bounds__(256) void colstats_kernel(const float* __restrict__ x) {
    int c  = blockIdx.x * 256 + threadIdx.x;
    int r0 = blockIdx.y * 256;
    float s = 0.f, s2 = 0.f;
    for (int r = r0; r < r0 + 256; r++) {
        float v = x[(size_t)r * NHD + c];
        s += v; s2 += v * v;
    }
    atomicAdd(&g_colsum[c], s);
    atomicAdd(&g_colsq[c], s2);
}

__global__ void colfin_kernel(const float* __restrict__ gamma, const float* __restrict__ beta) {
    int c = blockIdx.x * 256 + threadIdx.x;
    if (c >= NHD) return;
    float mu  = g_colsum[c] * (1.f / NN);
    float var = g_colsq[c] * (1.f / NN) - mu * mu;
    float rs  = rsqrtf(var + 1e-5f);
    float a   = rs * gamma[c];
    g_colA[c] = a;
    g_colB[c] = beta[c] - mu * a;
}

__global__ __launch_bounds__(256) void lnprelu_kernel(float* __restrict__ x, const float* __restrict__ pa) {
    int n = blockIdx.x;
    for (int c = threadIdx.x; c < NHD; c += 256) {
        float y = g_colA[c] * x[(size_t)n * NHD + c] + g_colB[c];
        x[(size_t)n * NHD + c] = y > 0.f ? y : pa[c] * y;
    }
}

// ---------------- head means / node_rep ----------------
__global__ __launch_bounds__(256) void headmean_kernel(const float* __restrict__ h, float* __restrict__ m) {
    int n = blockIdx.x;
    const float* r = h + (size_t)n * NHD;
    for (int f = threadIdx.x; f < NF; f += 256)
        m[(size_t)n * NF + f] = 0.25f * (r[f] + r[NF + f] + r[2 * NF + f] + r[3 * NF + f]);
}

__global__ __launch_bounds__(256) void repmax_kernel(const float* __restrict__ h) {
    int n = blockIdx.x;
    const float* r = h + (size_t)n * NHD;
    for (int f = threadIdx.x; f < NF; f += 256) {
        float m2 = 0.25f * (r[f] + r[NF + f] + r[2 * NF + f] + r[3 * NF + f]);
        g_rep[(size_t)n * NF + f] = fmaxf(g_m1[(size_t)n * NF + f], m2);
    }
}

// ---------------- sims: S[128 x 8192] = Qe @ rep^T (both K-contiguous) ----------------
__global__ __launch_bounds__(256) void simgemm_kernel(
    const float* __restrict__ Qe, const float* __restrict__ R)
{
    __shared__ float Qs[128][33];
    __shared__ float Rs[32][33];
    int tid = threadIdx.x;
    int n0 = blockIdx.x * 32;
    float acc[16];
#pragma unroll
    for (int i = 0; i < 16; i++) acc[i] = 0.f;
    int n = tid & 31, rb = tid >> 5;   // n: node within tile, rb: query base (0..7)

    for (int k0 = 0; k0 < ND; k0 += 32) {
#pragma unroll
        for (int t = 0; t < 16; t++) {
            int li = tid + t * 256;
            Qs[li >> 5][li & 31] = Qe[(size_t)(li >> 5) * ND + k0 + (li & 31)];
        }
#pragma unroll
        for (int t = 0; t < 4; t++) {
            int li = tid + t * 256;
            Rs[li >> 5][li & 31] = R[(size_t)(n0 + (li >> 5)) * ND + k0 + (li & 31)];
        }
        __syncthreads();
#pragma unroll
        for (int kk = 0; kk < 32; kk++) {
            float b = Rs[n][kk];
#pragma unroll
            for (int i = 0; i < 16; i++)
                acc[i] += Qs[rb + 8 * i][kk] * b;
        }
        __syncthreads();
    }
#pragma unroll
    for (int i = 0; i < 16; i++)
        g_S[(size_t)(rb + 8 * i) * NN + n0 + n] = acc[i];
}

// ---------------- output zero ----------------
__global__ void zeroout_kernel(float* out) {
    if (threadIdx.x < 3) out[threadIdx.x] = 0.f;
}

// ---------------- losses ----------------
__device__ __forceinline__ float warpSumF(float v) {
#pragma unroll
    for (int o = 16; o; o >>= 1) v += __shfl_xor_sync(0xffffffffu, v, o);
    return v;
}

__device__ __forceinline__ float blockSumF(float v, float* sred, int tid) {
    v = warpSumF(v);
    if ((tid & 31) == 0) sred[tid >> 5] = v;
    __syncthreads();
    if (tid < 32) {
        float x = (tid < 16) ? sred[tid] : 0.f;
        x = warpSumF(x);
        if (tid == 0) sred[0] = x;
    }
    __syncthreads();
    float r = sred[0];
    __syncthreads();
    return r;
}

__device__ __forceinline__ float blockMaxF(float v, float* sred, int tid) {
#pragma unroll
    for (int o = 16; o; o >>= 1) v = fmaxf(v, __shfl_xor_sync(0xffffffffu, v, o));
    if ((tid & 31) == 0) sred[tid >> 5] = v;
    __syncthreads();
    if (tid < 32) {
        float x = (tid < 16) ? sred[tid] : -INFINITY;
#pragma unroll
        for (int o = 16; o; o >>= 1) x = fmaxf(x, __shfl_xor_sync(0xffffffffu, x, o));
        if (tid == 0) sred[0] = x;
    }
    __syncthreads();
    float r = sred[0];
    __syncthreads();
    return r;
}

// bitonic sort, descending by key, ties broken by ascending idx (stable-equivalent)
__device__ void bitonic1024_desc(float* key, int* idx, int tid) {
    for (int k = 2; k <= 1024; k <<= 1) {
        for (int j = k >> 1; j > 0; j >>= 1) {
#pragma unroll 1
            for (int t = tid; t < 1024; t += 512) {
                int x = t ^ j;
                if (x > t) {
                    bool descSeg = ((t & k) == 0);
                    float ka = key[t], kb = key[x];
                    int   ia = idx[t], ib = idx[x];
                    bool aFirst = (ka > kb) || (ka == kb && ia < ib);
                    bool doSwap = descSeg ? (!aFirst) : aFirst;
                    if (doSwap) { key[t] = kb; key[x] = ka; idx[t] = ib; idx[x] = ia; }
                }
            }
            __syncthreads();
        }
    }
}

__global__ __launch_bounds__(512) void loss_kernel(const float* __restrict__ bert, float* __restrict__ out) {
    __shared__ float skey[1024];
    __shared__ int   sidx[1024];
    __shared__ float sred[16];
    __shared__ float sh_psim;
    int r = blockIdx.x;                 // 0..127 (graph-major: r = g*16+q)
    int g = r >> 4;
    int base = g * NPG;
    int tid = threadIdx.x;
    const float* Srow = g_S + (size_t)r * NN;

    // 1) sort bert scores descending -> order
    skey[tid]       = bert[(size_t)r * NPG + tid];       sidx[tid]       = tid;
    skey[tid + 512] = bert[(size_t)r * NPG + tid + 512]; sidx[tid + 512] = tid + 512;
    __syncthreads();
    bitonic1024_desc(skey, sidx, tid);

    // 2) gather sims in bert order; payload becomes bert rank
    int i0 = sidx[tid], i1 = sidx[tid + 512];
    float v0 = Srow[base + i0], v1 = Srow[base + i1];
    __syncthreads();
    skey[tid] = v0;       sidx[tid] = tid;
    skey[tid + 512] = v1; sidx[tid + 512] = tid + 512;
    if (tid == 0) sh_psim = v0;         // sim of bert-rank-0 item
    __syncthreads();

    // 3) sort by predicted sim descending (payload = bert rank)
    bitonic1024_desc(skey, sidx, tid);

    // 4) pairwise lambda-MRR over unordered pairs:
    //    t = min(yp_i - yp_j, 50); loss = softplus(-t) + (rank_i > rank_j ? t : 0)
    float L = 0.f;
    for (int i = 0; i < 1023; i++) {
        float yi = skey[i];
        int   pi = sidx[i];
        for (int j = i + 1 + tid; j < 1024; j += 512) {
            float s = yi - skey[j];
            float t = fminf(s, 50.f);
            float u = __logf(1.f + __expf(-t));
            L += u + ((pi > sidx[j]) ? t : 0.f);
        }
    }
    float Ltot = blockSumF(L, sred, tid);

    // 5) row-wide logsumexp (cl) and own-segment entropy
    float mx = -INFINITY;
    for (int c = tid; c < NN; c += 512) mx = fmaxf(mx, Srow[c]);
    float m = blockMaxF(mx, sred, tid);

    float se = 0.f, s1 = 0.f, s2 = 0.f;
    for (int c = tid; c < NN; c += 512) {
        float x = Srow[c] - m;
        float e = __expf(x);
        se += e;
        if (c >= base && c < base + NPG) { s1 += e; s2 += x * e; }
    }
    se = blockSumF(se, sred, tid);
    s1 = blockSumF(s1, sred, tid);
    s2 = blockSumF(s2, sred, tid);

    if (tid == 0) {
        float lse = m + __logf(se);
        float cl  = lse - sh_psim;                  // -log(pe/(pe+ne))
        float ent = __logf(s1) - s2 / s1;           // entropy of softmax over own nodes
        atomicAdd(out + 0, cl  * (1.f / 128.f));
        atomicAdd(out + 2, ent * (1.f / 128.f));
        atomicAdd(out + 1, Ltot * (1.f / 67043328.f)); // / (BG * Q * NPG*(NPG-1)/2)
    }
}

// ---------------- launch ----------------
extern "C" void kernel_launch(void* const* d_in, const int* in_sizes, int n_in,
                              void* d_out, int out_size) {
    const float* x      = (const float*)d_in[0];
    const int*   esrc   = (const int*)d_in[1];
    // d_in[2] = edge_dst (structure known: repeat(arange(N), 8)) — unused
    const float* qe     = (const float*)d_in[3];
    const float* bert   = (const float*)d_in[4];
    const float* W1     = (const float*)d_in[5];
    const float* al1    = (const float*)d_in[6];
    const float* ar1    = (const float*)d_in[7];
    const float* b1     = (const float*)d_in[8];
    const float* gamma1 = (const float*)d_in[9];
    const float* beta1  = (const float*)d_in[10];
    const float* pa1    = (const float*)d_in[11];
    const float* W2     = (const float*)d_in[12];
    const float* al2    = (const float*)d_in[13];
    const float* ar2    = (const float*)d_in[14];
    const float* b2     = (const float*)d_in[15];
    const float* gamma2 = (const float*)d_in[16];
    const float* beta2  = (const float*)d_in[17];
    const float* pa2    = (const float*)d_in[18];
    float* out = (float*)d_out;

    float *feat, *h, *el, *er, *m1, *rep;
    cudaGetSymbolAddress((void**)&feat, g_feat);
    cudaGetSymbolAddress((void**)&h,    g_h);
    cudaGetSymbolAddress((void**)&el,   g_el);
    cudaGetSymbolAddress((void**)&er,   g_er);
    cudaGetSymbolAddress((void**)&m1,   g_m1);
    cudaGetSymbolAddress((void**)&rep,  g_rep);

    cudaFuncSetAttribute(mma_gemm_kernel,
                         cudaFuncAttributeMaxDynamicSharedMemorySize, GEMM_SMEM);

    dim3 gGemm(NHD / GBN, NN / GBM);       // (24, 64)
    dim3 gStats(NHD / 256, NN / 256);      // (12, 32)

    zeroout_kernel<<<1, 32>>>(out);

    // ---- layer 1 ----
    mma_gemm_kernel<<<gGemm, 128, GEMM_SMEM>>>(x, W1, feat, ND, NHD);
    elr_kernel<<<(NN * NH) / 8, 256>>>(feat, al1, ar1, el, er);
    aggregate_kernel<<<NN, 256>>>(feat, el, er, esrc, b1, h);
    colzero_kernel<<<NHD / 256, 256>>>();
    colstats_kernel<<<gStats, 256>>>(h);
    colfin_kernel<<<NHD / 256, 256>>>(gamma1, beta1);
    lnprelu_kernel<<<NN, 256>>>(h, pa1);
    headmean_kernel<<<NN, 256>>>(h, m1);

    // ---- layer 2 ----
    mma_gemm_kernel<<<gGemm, 128, GEMM_SMEM>>>(h, W2, feat, NHD, NHD);
    elr_kernel<<<(NN * NH) / 8, 256>>>(feat, al2, ar2, el, er);
    aggregate_kernel<<<NN, 256>>>(feat, el, er, esrc, b2, h);
    colzero_kernel<<<NHD / 256, 256>>>();
    colstats_kernel<<<gStats, 256>>>(h);
    colfin_kernel<<<NHD / 256, 256>>>(gamma2, beta2);
    lnprelu_kernel<<<NN, 256>>>(h, pa2);
    repmax_kernel<<<NN, 256>>>(h);

    // ---- similarities + losses ----
    simgemm_kernel<<<NN / 32, 256>>>(qe, rep);
    loss_kernel<<<NROW, 512>>>(bert, out);
}

// round 6
// speedup vs baseline: 3.7741x; 1.4215x over previous
#include <cuda_runtime.h>
#include <cuda_bf16.h>
#include <math.h>
#include <stdint.h>

#define NN   8192
#define DEG  8
#define NH   4
#define NF   768
#define NHD  3072
#define ND   768
#define NBG  8
#define NPG  1024
#define NQ   16
#define NROW 128   // NBG*NQ

// ---------------- scratch (static device memory; no allocation) ----------------
__device__ float g_feat[(size_t)NN * NHD];       // GEMM output (feat) per layer
__device__ float g_h[(size_t)NN * NHD];          // aggregate output (pre-LN)
__device__ __nv_bfloat16 g_a16[(size_t)NN * NHD];    // bf16 GEMM A operand
__device__ __nv_bfloat16 g_bT[(size_t)NHD * NHD];    // bf16 transposed weights [M][K]
__device__ float g_el[NN * NH];
__device__ float g_er[NN * NH];
__device__ float g_m1[(size_t)NN * NF];
__device__ float g_rep[(size_t)NN * NF];
__device__ float g_S[(size_t)NROW * NN];
__device__ float g_colsum[NHD];
__device__ float g_colsq[NHD];
__device__ float g_colA[NHD];
__device__ float g_colB[NHD];

// ================= bf16 tensor-core GEMM (mma.sync m16n8k16) =================
// C[N x 3072] = A[N x K](bf16) @ Bt[3072 x K]^T(bf16), fp32 accum.
// 128 threads = 4 warps (2x2), block tile 128x128x32, warp tile 64x64.
// Both smem tiles are [128 rows][32 bf16] padded to 20 words (40 bf16) per row:
//   word index (row*20 + tig) mod 32 distinct over (g,tig) -> conflict-free,
//   80-byte rows keep every 16B cp.async chunk aligned.
#define BK2   32
#define ROWW  20                    // 32-bit words per smem row
#define TILE_W (128 * ROWW)         // words per tile buffer
#define GEMM_SMEM (4 * TILE_W * 4)  // 2 operands x 2 buffers

__device__ __forceinline__ void cp_async16(void* dst, const void* src) {
    unsigned int s = (unsigned int)__cvta_generic_to_shared(dst);
    asm volatile("cp.async.cg.shared.global [%0], [%1], 16;" :: "r"(s), "l"(src));
}

__device__ __forceinline__ void bf16_load_tiles(
    uint32_t* As, uint32_t* Bs, const __nv_bfloat16* Ab, const __nv_bfloat16* Bb,
    int buf, int k0, int tid, int K)
{
#pragma unroll
    for (int i = 0; i < 4; i++) {
        int li = tid + i * 128;          // 0..511
        int r = li >> 2, ch = li & 3;    // 128 rows x 4 16B-chunks
        cp_async16((char*)(As + buf * TILE_W) + r * 80 + ch * 16,
                   Ab + (size_t)r * K + k0 + ch * 8);
    }
#pragma unroll
    for (int i = 0; i < 4; i++) {
        int li = tid + i * 128;
        int r = li >> 2, ch = li & 3;
        cp_async16((char*)(Bs + buf * TILE_W) + r * 80 + ch * 16,
                   Bb + (size_t)r * K + k0 + ch * 8);
    }
    asm volatile("cp.async.commit_group;");
}

__global__ __launch_bounds__(128) void bf16_gemm_kernel(
    const __nv_bfloat16* __restrict__ A, const __nv_bfloat16* __restrict__ Bt,
    float* __restrict__ C, int K)
{
    extern __shared__ uint32_t sm[];
    uint32_t* As = sm;                 // 2 x TILE_W
    uint32_t* Bs = sm + 2 * TILE_W;    // 2 x TILE_W
    int tid = threadIdx.x;
    int lane = tid & 31, wid = tid >> 5;
    int wm = (wid & 1) * 64, wn = (wid >> 1) * 64;
    int g = lane >> 2, tig = lane & 3;
    const __nv_bfloat16* Ab = A + (size_t)blockIdx.y * 128 * K;
    const __nv_bfloat16* Bb = Bt + (size_t)blockIdx.x * 128 * K;

    float c[4][8][4];
#pragma unroll
    for (int mt = 0; mt < 4; mt++)
#pragma unroll
        for (int nt = 0; nt < 8; nt++)
#pragma unroll
            for (int i = 0; i < 4; i++) c[mt][nt][i] = 0.f;

    bf16_load_tiles(As, Bs, Ab, Bb, 0, 0, tid, K);
    int nk = K / BK2;
    for (int t = 0; t < nk; t++) {
        int buf = t & 1;
        asm volatile("cp.async.wait_group 0;" ::: "memory");
        __syncthreads();
        if (t + 1 < nk)
            bf16_load_tiles(As, Bs, Ab, Bb, buf ^ 1, (t + 1) * BK2, tid, K);
        const uint32_t* A2 = As + buf * TILE_W;
        const uint32_t* B2 = Bs + buf * TILE_W;
#pragma unroll
        for (int kk2 = 0; kk2 < 2; kk2++) {
            int kw = kk2 * 8;
            unsigned a[4][4], b[8][2];
#pragma unroll
            for (int mt = 0; mt < 4; mt++) {
                int base = (wm + mt * 16 + g) * ROWW + kw + tig;
                a[mt][0] = A2[base];
                a[mt][1] = A2[base + 8 * ROWW];
                a[mt][2] = A2[base + 4];
                a[mt][3] = A2[base + 8 * ROWW + 4];
            }
#pragma unroll
            for (int nt = 0; nt < 8; nt++) {
                int base = (wn + nt * 8 + g) * ROWW + kw + tig;
                b[nt][0] = B2[base];
                b[nt][1] = B2[base + 4];
            }
#pragma unroll
            for (int mt = 0; mt < 4; mt++)
#pragma unroll
                for (int nt = 0; nt < 8; nt++)
                    asm volatile(
                        "mma.sync.aligned.m16n8k16.row.col.f32.bf16.bf16.f32 "
                        "{%0,%1,%2,%3}, {%4,%5,%6,%7}, {%8,%9}, {%0,%1,%2,%3};"
                        : "+f"(c[mt][nt][0]), "+f"(c[mt][nt][1]),
                          "+f"(c[mt][nt][2]), "+f"(c[mt][nt][3])
                        : "r"(a[mt][0]), "r"(a[mt][1]), "r"(a[mt][2]), "r"(a[mt][3]),
                          "r"(b[nt][0]), "r"(b[nt][1]));
        }
        __syncthreads();
    }

    float* Cb = C + (size_t)(blockIdx.y * 128) * NHD + blockIdx.x * 128;
#pragma unroll
    for (int mt = 0; mt < 4; mt++)
#pragma unroll
        for (int nt = 0; nt < 8; nt++) {
            int row = wm + mt * 16 + g;
            int col = wn + nt * 8 + 2 * tig;
            *(float2*)(Cb + (size_t)row * NHD + col) =
                make_float2(c[mt][nt][0], c[mt][nt][1]);
            *(float2*)(Cb + (size_t)(row + 8) * NHD + col) =
                make_float2(c[mt][nt][2], c[mt][nt][3]);
        }
}

// ---------------- fp32 -> bf16 convert ----------------
__global__ void cvt16_kernel(const float* __restrict__ x, __nv_bfloat16* __restrict__ o, int n) {
    int i = blockIdx.x * 256 + threadIdx.x;
    if (i < n) o[i] = __float2bfloat16(x[i]);
}

// ---------------- W[K][M] -> Bt[M][K] bf16 transpose ----------------
__global__ __launch_bounds__(256) void wtrans_kernel(
    const float* __restrict__ W, __nv_bfloat16* __restrict__ Bt, int K, int M)
{
    __shared__ float t[32][33];
    int m0 = blockIdx.x * 32, k0 = blockIdx.y * 32;
    int tx = threadIdx.x & 31, ty = threadIdx.x >> 5;  // 32 x 8
#pragma unroll
    for (int i = 0; i < 32; i += 8)
        t[ty + i][tx] = W[(size_t)(k0 + ty + i) * M + m0 + tx];
    __syncthreads();
#pragma unroll
    for (int i = 0; i < 32; i += 8)
        Bt[(size_t)(m0 + ty + i) * K + k0 + tx] = __float2bfloat16(t[tx][ty + i]);
}

// ---------------- el/er: per (n,h) dot of feat row with attn vectors ----------------
__global__ __launch_bounds__(256) void elr_kernel(
    const float* __restrict__ feat, const float* __restrict__ al,
    const float* __restrict__ ar, float* __restrict__ el, float* __restrict__ er)
{
    int gw = (blockIdx.x * blockDim.x + threadIdx.x) >> 5;
    int lane = threadIdx.x & 31;
    if (gw >= NN * NH) return;
    int n = gw >> 2, h = gw & 3;
    const float* f   = feat + (size_t)n * NHD + h * NF;
    const float* alh = al + h * NF;
    const float* arh = ar + h * NF;
    float sl = 0.f, sr = 0.f;
    for (int i = lane; i < NF; i += 32) {
        float v = f[i];
        sl += v * alh[i];
        sr += v * arh[i];
    }
#pragma unroll
    for (int o = 16; o; o >>= 1) {
        sl += __shfl_xor_sync(0xffffffffu, sl, o);
        sr += __shfl_xor_sync(0xffffffffu, sr, o);
    }
    if (lane == 0) { el[gw] = sl; er[gw] = sr; }
}

// ---------------- edge softmax + aggregation (+bias) ----------------
__global__ __launch_bounds__(256) void aggregate_kernel(
    const float* __restrict__ feat, const float* __restrict__ el,
    const float* __restrict__ er, const int* __restrict__ esrc,
    const float* __restrict__ bias, float* __restrict__ out)
{
    int n = blockIdx.x;
    __shared__ int   ssrc[DEG];
    __shared__ float salpha[NH * DEG];
    int tid = threadIdx.x;
    if (tid < DEG) ssrc[tid] = esrc[n * DEG + tid];
    __syncthreads();
    if (tid < 32) {
        int h = tid >> 3, k = tid & 7;
        float e = el[ssrc[k] * NH + h] + er[n * NH + h];
        e = e > 0.f ? e : 0.2f * e;
        float m = e;
#pragma unroll
        for (int o = 4; o; o >>= 1) m = fmaxf(m, __shfl_xor_sync(0xffffffffu, m, o));
        float a = __expf(e - m);
        float s = a;
#pragma unroll
        for (int o = 4; o; o >>= 1) s += __shfl_xor_sync(0xffffffffu, s, o);
        salpha[tid] = a / s;
    }
    __syncthreads();
    for (int c = tid; c < NHD; c += 256) {
        int h = c / NF;
        float acc = bias[c];
#pragma unroll
        for (int k = 0; k < DEG; k++)
            acc += salpha[h * DEG + k] * feat[(size_t)ssrc[k] * NHD + c];
        out[(size_t)n * NHD + c] = acc;
    }
}

// ---------------- column stats (LayerNorm over axis 0) ----------------
__global__ void colzero_kernel() {
    int c = blockIdx.x * 256 + threadIdx.x;
    if (c < NHD) { g_colsum[c] = 0.f; g_colsq[c] = 0.f; }
}

__global__ __launch_bounds__(256) void colstats_kernel(const float* __restrict__ x) {
    int c  = blockIdx.x * 256 + threadIdx.x;
    int r0 = blockIdx.y * 256;
    float s = 0.f, s2 = 0.f;
    for (int r = r0; r < r0 + 256; r++) {
        float v = x[(size_t)r * NHD + c];
        s += v; s2 += v * v;
    }
    atomicAdd(&g_colsum[c], s);
    atomicAdd(&g_colsq[c], s2);
}

__global__ void colfin_kernel(const float* __restrict__ gamma, const float* __restrict__ beta) {
    int c = blockIdx.x * 256 + threadIdx.x;
    if (c >= NHD) return;
    float mu  = g_colsum[c] * (1.f / NN);
    float var = g_colsq[c] * (1.f / NN) - mu * mu;
    float rs  = rsqrtf(var + 1e-5f);
    float a   = rs * gamma[c];
    g_colA[c] = a;
    g_colB[c] = beta[c] - mu * a;
}

// ---------------- LN + PReLU epilogues (fused bf16 convert / head-mean) ----------------
__global__ __launch_bounds__(256) void lnfuse1_kernel(
    const float* __restrict__ h, const float* __restrict__ pa,
    __nv_bfloat16* __restrict__ a16, float* __restrict__ m1)
{
    int n = blockIdx.x;
    for (int f = threadIdx.x; f < NF; f += 256) {
        float s = 0.f;
#pragma unroll
        for (int hh = 0; hh < 4; hh++) {
            int c = hh * NF + f;
            float y = g_colA[c] * h[(size_t)n * NHD + c] + g_colB[c];
            y = y > 0.f ? y : pa[c] * y;
            a16[(size_t)n * NHD + c] = __float2bfloat16(y);
            s += y;
        }
        m1[(size_t)n * NF + f] = 0.25f * s;
    }
}

__global__ __launch_bounds__(256) void lnfuse2_kernel(
    const float* __restrict__ h, const float* __restrict__ pa)
{
    int n = blockIdx.x;
    for (int f = threadIdx.x; f < NF; f += 256) {
        float s = 0.f;
#pragma unroll
        for (int hh = 0; hh < 4; hh++) {
            int c = hh * NF + f;
            float y = g_colA[c] * h[(size_t)n * NHD + c] + g_colB[c];
            y = y > 0.f ? y : pa[c] * y;
            s += y;
        }
        g_rep[(size_t)n * NF + f] = fmaxf(g_m1[(size_t)n * NF + f], 0.25f * s);
    }
}

// ---------------- sims: S[128 x 8192] = Qe @ rep^T ----------------
__global__ __launch_bounds__(256) void simgemm_kernel(
    const float* __restrict__ Qe, const float* __restrict__ R)
{
    __shared__ float Qs[128][33];
    __shared__ float Rs[32][33];
    int tid = threadIdx.x;
    int n0 = blockIdx.x * 32;
    float acc[16];
#pragma unroll
    for (int i = 0; i < 16; i++) acc[i] = 0.f;
    int n = tid & 31, rb = tid >> 5;

    for (int k0 = 0; k0 < ND; k0 += 32) {
#pragma unroll
        for (int t = 0; t < 16; t++) {
            int li = tid + t * 256;
            Qs[li >> 5][li & 31] = Qe[(size_t)(li >> 5) * ND + k0 + (li & 31)];
        }
#pragma unroll
        for (int t = 0; t < 4; t++) {
            int li = tid + t * 256;
            Rs[li >> 5][li & 31] = R[(size_t)(n0 + (li >> 5)) * ND + k0 + (li & 31)];
        }
        __syncthreads();
#pragma unroll
        for (int kk = 0; kk < 32; kk++) {
            float b = Rs[n][kk];
#pragma unroll
            for (int i = 0; i < 16; i++)
                acc[i] += Qs[rb + 8 * i][kk] * b;
        }
        __syncthreads();
    }
#pragma unroll
    for (int i = 0; i < 16; i++)
        g_S[(size_t)(rb + 8 * i) * NN + n0 + n] = acc[i];
}

// ---------------- output zero ----------------
__global__ void zeroout_kernel(float* out) {
    if (threadIdx.x < 3) out[threadIdx.x] = 0.f;
}

// ---------------- losses ----------------
__device__ __forceinline__ float warpSumF(float v) {
#pragma unroll
    for (int o = 16; o; o >>= 1) v += __shfl_xor_sync(0xffffffffu, v, o);
    return v;
}

__device__ __forceinline__ float blockSumF(float v, float* sred, int tid) {
    v = warpSumF(v);
    if ((tid & 31) == 0) sred[tid >> 5] = v;
    __syncthreads();
    if (tid < 32) {
        float x = (tid < 16) ? sred[tid] : 0.f;
        x = warpSumF(x);
        if (tid == 0) sred[0] = x;
    }
    __syncthreads();
    float r = sred[0];
    __syncthreads();
    return r;
}

__device__ __forceinline__ float blockMaxF(float v, float* sred, int tid) {
#pragma unroll
    for (int o = 16; o; o >>= 1) v = fmaxf(v, __shfl_xor_sync(0xffffffffu, v, o));
    if ((tid & 31) == 0) sred[tid >> 5] = v;
    __syncthreads();
    if (tid < 32) {
        float x = (tid < 16) ? sred[tid] : -INFINITY;
#pragma unroll
        for (int o = 16; o; o >>= 1) x = fmaxf(x, __shfl_xor_sync(0xffffffffu, x, o));
        if (tid == 0) sred[0] = x;
    }
    __syncthreads();
    float r = sred[0];
    __syncthreads();
    return r;
}

__device__ void bitonic1024_desc(float* key, int* idx, int tid) {
    for (int k = 2; k <= 1024; k <<= 1) {
        for (int j = k >> 1; j > 0; j >>= 1) {
#pragma unroll 1
            for (int t = tid; t < 1024; t += 512) {
                int x = t ^ j;
                if (x > t) {
                    bool descSeg = ((t & k) == 0);
                    float ka = key[t], kb = key[x];
                    int   ia = idx[t], ib = idx[x];
                    bool aFirst = (ka > kb) || (ka == kb && ia < ib);
                    bool doSwap = descSeg ? (!aFirst) : aFirst;
                    if (doSwap) { key[t] = kb; key[x] = ka; idx[t] = ib; idx[x] = ia; }
                }
            }
            __syncthreads();
        }
    }
}

__global__ __launch_bounds__(512) void loss_kernel(const float* __restrict__ bert, float* __restrict__ out) {
    __shared__ float skey[1024];
    __shared__ int   sidx[1024];
    __shared__ float sred[16];
    __shared__ float sh_psim;
    int r = blockIdx.x;
    int g = r >> 4;
    int base = g * NPG;
    int tid = threadIdx.x;
    const float* Srow = g_S + (size_t)r * NN;

    skey[tid]       = bert[(size_t)r * NPG + tid];       sidx[tid]       = tid;
    skey[tid + 512] = bert[(size_t)r * NPG + tid + 512]; sidx[tid + 512] = tid + 512;
    __syncthreads();
    bitonic1024_desc(skey, sidx, tid);

    int i0 = sidx[tid], i1 = sidx[tid + 512];
    float v0 = Srow[base + i0], v1 = Srow[base + i1];
    __syncthreads();
    skey[tid] = v0;       sidx[tid] = tid;
    skey[tid + 512] = v1; sidx[tid + 512] = tid + 512;
    if (tid == 0) sh_psim = v0;
    __syncthreads();

    bitonic1024_desc(skey, sidx, tid);

    float L = 0.f;
    for (int i = 0; i < 1023; i++) {
        float yi = skey[i];
        int   pi = sidx[i];
        for (int j = i + 1 + tid; j < 1024; j += 512) {
            float s = yi - skey[j];
            float t = fminf(s, 50.f);
            float u = __logf(1.f + __expf(-t));
            L += u + ((pi > sidx[j]) ? t : 0.f);
        }
    }
    float Ltot = blockSumF(L, sred, tid);

    float mx = -INFINITY;
    for (int c = tid; c < NN; c += 512) mx = fmaxf(mx, Srow[c]);
    float m = blockMaxF(mx, sred, tid);

    float se = 0.f, s1 = 0.f, s2 = 0.f;
    for (int c = tid; c < NN; c += 512) {
        float x = Srow[c] - m;
        float e = __expf(x);
        se += e;
        if (c >= base && c < base + NPG) { s1 += e; s2 += x * e; }
    }
    se = blockSumF(se, sred, tid);
    s1 = blockSumF(s1, sred, tid);
    s2 = blockSumF(s2, sred, tid);

    if (tid == 0) {
        float lse = m + __logf(se);
        float cl  = lse - sh_psim;
        float ent = __logf(s1) - s2 / s1;
        atomicAdd(out + 0, cl  * (1.f / 128.f));
        atomicAdd(out + 2, ent * (1.f / 128.f));
        atomicAdd(out + 1, Ltot * (1.f / 67043328.f));
    }
}

// ---------------- launch ----------------
extern "C" void kernel_launch(void* const* d_in, const int* in_sizes, int n_in,
                              void* d_out, int out_size) {
    const float* x      = (const float*)d_in[0];
    const int*   esrc   = (const int*)d_in[1];
    const float* qe     = (const float*)d_in[3];
    const float* bert   = (const float*)d_in[4];
    const float* W1     = (const float*)d_in[5];
    const float* al1    = (const float*)d_in[6];
    const float* ar1    = (const float*)d_in[7];
    const float* b1     = (const float*)d_in[8];
    const float* gamma1 = (const float*)d_in[9];
    const float* beta1  = (const float*)d_in[10];
    const float* pa1    = (const float*)d_in[11];
    const float* W2     = (const float*)d_in[12];
    const float* al2    = (const float*)d_in[13];
    const float* ar2    = (const float*)d_in[14];
    const float* b2     = (const float*)d_in[15];
    const float* gamma2 = (const float*)d_in[16];
    const float* beta2  = (const float*)d_in[17];
    const float* pa2    = (const float*)d_in[18];
    float* out = (float*)d_out;

    float *feat, *h, *el, *er, *m1, *rep;
    __nv_bfloat16 *a16, *bT;
    cudaGetSymbolAddress((void**)&feat, g_feat);
    cudaGetSymbolAddress((void**)&h,    g_h);
    cudaGetSymbolAddress((void**)&el,   g_el);
    cudaGetSymbolAddress((void**)&er,   g_er);
    cudaGetSymbolAddress((void**)&m1,   g_m1);
    cudaGetSymbolAddress((void**)&rep,  g_rep);
    cudaGetSymbolAddress((void**)&a16,  g_a16);
    cudaGetSymbolAddress((void**)&bT,   g_bT);

    cudaFuncSetAttribute(bf16_gemm_kernel,
                         cudaFuncAttributeMaxDynamicSharedMemorySize, GEMM_SMEM);

    dim3 gGemm(NHD / 128, NN / 128);       // (24, 64)
    dim3 gStats(NHD / 256, NN / 256);      // (12, 32)

    zeroout_kernel<<<1, 32>>>(out);

    // ---- layer 1 ----
    cvt16_kernel<<<(NN * ND + 255) / 256, 256>>>(x, a16, NN * ND);
    wtrans_kernel<<<dim3(NHD / 32, ND / 32), 256>>>(W1, bT, ND, NHD);
    bf16_gemm_kernel<<<gGemm, 128, GEMM_SMEM>>>(a16, bT, feat, ND);
    elr_kernel<<<(NN * NH) / 8, 256>>>(feat, al1, ar1, el, er);
    aggregate_kernel<<<NN, 256>>>(feat, el, er, esrc, b1, h);
    colzero_kernel<<<NHD / 256, 256>>>();
    colstats_kernel<<<gStats, 256>>>(h);
    colfin_kernel<<<NHD / 256, 256>>>(gamma1, beta1);
    lnfuse1_kernel<<<NN, 256>>>(h, pa1, a16, m1);

    // ---- layer 2 ----
    wtrans_kernel<<<dim3(NHD / 32, NHD / 32), 256>>>(W2, bT, NHD, NHD);
    bf16_gemm_kernel<<<gGemm, 128, GEMM_SMEM>>>(a16, bT, feat, NHD);
    elr_kernel<<<(NN * NH) / 8, 256>>>(feat, al2, ar2, el, er);
    aggregate_kernel<<<NN, 256>>>(feat, el, er, esrc, b2, h);
    colzero_kernel<<<NHD / 256, 256>>>();
    colstats_kernel<<<gStats, 256>>>(h);
    colfin_kernel<<<NHD / 256, 256>>>(gamma2, beta2);
    lnfuse2_kernel<<<NN, 256>>>(h, pa2);

    // ---- similarities + losses ----
    simgemm_kernel<<<NN / 32, 256>>>(qe, rep);
    loss_kernel<<<NROW, 512>>>(bert, out);
}